// round 14
// baseline (speedup 1.0000x reference)
#include <cuda_runtime.h>
#include <cuda_fp16.h>

#define FM_H 38
#define FM_W 50
#define N_ROI 512
#define POOL 7
#define FM_ELEMS (FM_H * FM_W * 512)
#define N_CELLS (N_ROI * POOL * POOL)      // 25088
#define N_ROWBLK (N_ROI * POOL)            // 3584
#define N8 (FM_ELEMS / 8)                  // 121600
#define N8BLOCKS ((N8 + 255) / 256)        // 475

// Static scratch (allocation-free).
__device__ __align__(16) static __half g_fmh[FM_ELEMS];   // fp16 feature map
__device__ static int4  g_cols[N_CELLS];       // premult col offsets (x*128)
__device__ static uint4 g_waa[N_CELLS];        // weight quads per point
__device__ static uint4 g_wab[N_CELLS];
__device__ static uint4 g_wba[N_CELLS];
__device__ static uint4 g_wbb[N_CELLS];
__device__ static int4  g_rows[N_ROWBLK];      // premult row offsets (y*50*128)
__device__ static int   g_mode[N_ROWBLK];      // row-dedup mode 0/1/2

__device__ __forceinline__ unsigned pack_h2(float f) {
    __half2 h = __float2half2_rn(f);
    return *reinterpret_cast<unsigned*>(&h);
}

// ---- merged fp32->fp16 convert + per-cell parameter precompute ----
__global__ __launch_bounds__(256) void prep_kernel(
    const float* __restrict__ fm, const float* __restrict__ rois)
{
    const int b = blockIdx.x;
    if (b < N8BLOCKS) {
        const int i = (b * 256 + threadIdx.x) * 2;
        const float4 v0 = ((const float4*)fm)[i];
        const float4 v1 = ((const float4*)fm)[i + 1];
        __half2 a0 = __floats2half2_rn(v0.x, v0.y);
        __half2 a1 = __floats2half2_rn(v0.z, v0.w);
        __half2 b0 = __floats2half2_rn(v1.x, v1.y);
        __half2 b1 = __floats2half2_rn(v1.z, v1.w);
        uint4 u;
        u.x = *reinterpret_cast<unsigned*>(&a0);
        u.y = *reinterpret_cast<unsigned*>(&a1);
        u.z = *reinterpret_cast<unsigned*>(&b0);
        u.w = *reinterpret_cast<unsigned*>(&b1);
        ((uint4*)g_fmh)[i >> 1] = u;
        return;
    }
    const int idx = (b - N8BLOCKS) * 256 + threadIdx.x;   // cell id
    if (idx >= N_CELLS) return;
    const int roi = idx / (POOL * POOL);
    const int rem = idx - roi * POOL * POOL;
    const int py  = rem / POOL;
    const int px  = rem - py * POOL;

    const float* r = rois + roi * 5;
    const float x1n = r[1] * (1.0f / 800.0f);
    const float y1n = r[2] * (1.0f / 600.0f);
    const float x2n = r[3] * (1.0f / 800.0f);
    const float y2n = r[4] * (1.0f / 600.0f);
    const float dy = y2n - y1n;
    const float dx = x2n - x1n;

    int ya0, ya1, yb0, yb1;
    float wya, wyb;
    {
        const float tya = (float)(2 * py) * (1.0f / 13.0f);
        const float ysa = (y1n + tya * dy) * (float)(FM_H - 1);
        const float yfa = floorf(ysa);
        int y0 = (int)yfa; y0 = min(max(y0, 0), FM_H - 1);
        ya0 = y0; ya1 = min(y0 + 1, FM_H - 1); wya = ysa - yfa;

        const float tyb = (float)(2 * py + 1) * (1.0f / 13.0f);
        const float ysb = (y1n + tyb * dy) * (float)(FM_H - 1);
        const float yfb = floorf(ysb);
        int y1 = (int)yfb; y1 = min(max(y1, 0), FM_H - 1);
        yb0 = y1; yb1 = min(y1 + 1, FM_H - 1); wyb = ysb - yfb;
    }
    const float uya = 1.0f - wya;
    const float uyb = 1.0f - wyb;

    int mode, r2 = 0, r3 = 0;
    float waP = uya, waQ = wya, wbP, wbQ;
    if (yb0 == ya0) {
        mode = 0; wbP = uyb; wbQ = wyb;
    } else if (yb0 == ya1) {
        if (yb1 == yb0) { mode = 0; wbP = 0.0f; wbQ = uyb + wyb; }
        else { mode = 1; r2 = yb1; wbP = uyb; wbQ = wyb; }
    } else {
        mode = 2; r2 = yb0; r3 = yb1; wbP = uyb; wbQ = wyb;
    }
    if (px == 0) {
        const int rb = roi * POOL + py;
        g_rows[rb] = make_int4(ya0 * (FM_W * 128), ya1 * (FM_W * 128),
                               r2 * (FM_W * 128), r3 * (FM_W * 128));
        g_mode[rb] = mode;
    }

    int x0a, x1a, x0b, x1b;
    float wxa, wxb;
    {
        const float txa = (float)(2 * px) * (1.0f / 13.0f);
        const float xsa = (x1n + txa * dx) * (float)(FM_W - 1);
        const float xfa = floorf(xsa);
        int x0 = (int)xfa; x0 = min(max(x0, 0), FM_W - 1);
        x0a = x0; x1a = min(x0 + 1, FM_W - 1); wxa = xsa - xfa;

        const float txb = (float)(2 * px + 1) * (1.0f / 13.0f);
        const float xsb = (x1n + txb * dx) * (float)(FM_W - 1);
        const float xfb = floorf(xsb);
        int x1 = (int)xfb; x1 = min(max(x1, 0), FM_W - 1);
        x0b = x1; x1b = min(x1 + 1, FM_W - 1); wxb = xsb - xfb;
    }
    const float uxa = 1.0f - wxa;
    const float uxb = 1.0f - wxb;

    g_cols[idx] = make_int4(x0a * 128, x1a * 128, x0b * 128, x1b * 128);

    g_waa[idx] = make_uint4(pack_h2(waP * uxa), pack_h2(waP * wxa),
                            pack_h2(waQ * uxa), pack_h2(waQ * wxa));
    g_wab[idx] = make_uint4(pack_h2(waP * uxb), pack_h2(waP * wxb),
                            pack_h2(waQ * uxb), pack_h2(waQ * wxb));
    g_wba[idx] = make_uint4(pack_h2(wbP * uxa), pack_h2(wbP * wxa),
                            pack_h2(wbQ * uxa), pack_h2(wbQ * wxa));
    g_wbb[idx] = make_uint4(pack_h2(wbP * uxb), pack_h2(wbP * wxb),
                            pack_h2(wbQ * uxb), pack_h2(wbQ * wxb));
}

// ---- half4 helpers (all loads via the read-only __ldg path) ----
struct h4 { __half2 a, b; };

__device__ __forceinline__ h4 ld_h4(const uint2* __restrict__ p) {
    const uint2 u = __ldg(p);              // LDG.64.CONSTANT (hoistable)
    h4 v;
    v.a = *reinterpret_cast<const __half2*>(&u.x);
    v.b = *reinterpret_cast<const __half2*>(&u.y);
    return v;
}

__device__ __forceinline__ __half2 as_h2(unsigned u) {
    return *reinterpret_cast<__half2*>(&u);
}

__device__ __forceinline__ h4 quad4h(h4 A, h4 B, h4 C, h4 D,
                                     __half2 w0, __half2 w1, __half2 w2, __half2 w3) {
    h4 r;
    r.a = __hfma2(D.a, w3, __hfma2(C.a, w2, __hfma2(B.a, w1, __hmul2(A.a, w0))));
    r.b = __hfma2(D.b, w3, __hfma2(C.b, w2, __hfma2(B.b, w1, __hmul2(A.b, w0))));
    return r;
}

__device__ __forceinline__ h4 max4h(h4 x, h4 y) {
    h4 r;
    r.a = __hmax2(x.a, y.a);
    r.b = __hmax2(x.b, y.b);
    return r;
}

// MODE 0: rows (r0,r1) for both point pairs. MODE 1: pair-b on (r1,r2).
// MODE 2: pair-b on (r2,r3). Straight-line across 7 cells. Params are
// software-pipelined one cell ahead so their latency overlaps compute.
template <int MODE>
__device__ __forceinline__ void run_row(
    const uint2* __restrict__ fmt, float4* __restrict__ outp,
    const int4* __restrict__ colsp,
    const uint4* __restrict__ waa, const uint4* __restrict__ wab,
    const uint4* __restrict__ wba, const uint4* __restrict__ wbb,
    int4 rows)
{
    // prologue: params for cell 0
    int4  c   = __ldg(colsp);
    uint4 wAa = __ldg(waa);
    uint4 wAb = __ldg(wab);
    uint4 wBa = __ldg(wba);
    uint4 wBb = __ldg(wbb);

#pragma unroll
    for (int px = 0; px < POOL; ++px) {
        // prefetch next cell's params (overlaps this cell's loads/compute)
        int4 c_n; uint4 wAa_n, wAb_n, wBa_n, wBb_n;
        if (px < POOL - 1) {
            c_n   = __ldg(colsp + px + 1);
            wAa_n = __ldg(waa + px + 1);
            wAb_n = __ldg(wab + px + 1);
            wBa_n = __ldg(wba + px + 1);
            wBb_n = __ldg(wbb + px + 1);
        }

        const h4 vA0a = ld_h4(fmt + (rows.x + c.x));
        const h4 vA1a = ld_h4(fmt + (rows.x + c.y));
        const h4 vA0b = ld_h4(fmt + (rows.x + c.z));
        const h4 vA1b = ld_h4(fmt + (rows.x + c.w));
        const h4 vB0a = ld_h4(fmt + (rows.y + c.x));
        const h4 vB1a = ld_h4(fmt + (rows.y + c.y));
        const h4 vB0b = ld_h4(fmt + (rows.y + c.z));
        const h4 vB1b = ld_h4(fmt + (rows.y + c.w));

        h4 vC0a, vC1a, vC0b, vC1b, vD0a, vD1a, vD0b, vD1b;
        if (MODE == 0) {
            vC0a = vA0a; vC1a = vA1a; vC0b = vA0b; vC1b = vA1b;
            vD0a = vB0a; vD1a = vB1a; vD0b = vB0b; vD1b = vB1b;
        } else if (MODE == 1) {
            vC0a = vB0a; vC1a = vB1a; vC0b = vB0b; vC1b = vB1b;
            vD0a = ld_h4(fmt + (rows.z + c.x));
            vD1a = ld_h4(fmt + (rows.z + c.y));
            vD0b = ld_h4(fmt + (rows.z + c.z));
            vD1b = ld_h4(fmt + (rows.z + c.w));
        } else {
            vC0a = ld_h4(fmt + (rows.z + c.x));
            vC1a = ld_h4(fmt + (rows.z + c.y));
            vC0b = ld_h4(fmt + (rows.z + c.z));
            vC1b = ld_h4(fmt + (rows.z + c.w));
            vD0a = ld_h4(fmt + (rows.w + c.x));
            vD1a = ld_h4(fmt + (rows.w + c.y));
            vD0b = ld_h4(fmt + (rows.w + c.z));
            vD1b = ld_h4(fmt + (rows.w + c.w));
        }

        const h4 s_aa = quad4h(vA0a, vA1a, vB0a, vB1a,
                               as_h2(wAa.x), as_h2(wAa.y), as_h2(wAa.z), as_h2(wAa.w));
        const h4 s_ab = quad4h(vA0b, vA1b, vB0b, vB1b,
                               as_h2(wAb.x), as_h2(wAb.y), as_h2(wAb.z), as_h2(wAb.w));
        const h4 s_ba = quad4h(vC0a, vC1a, vD0a, vD1a,
                               as_h2(wBa.x), as_h2(wBa.y), as_h2(wBa.z), as_h2(wBa.w));
        const h4 s_bb = quad4h(vC0b, vC1b, vD0b, vD1b,
                               as_h2(wBb.x), as_h2(wBb.y), as_h2(wBb.z), as_h2(wBb.w));

        const h4 m = max4h(max4h(s_aa, s_ab), max4h(s_ba, s_bb));
        const float2 lo = __half22float2(m.a);
        const float2 hi = __half22float2(m.b);
        outp[px * 128] = make_float4(lo.x, lo.y, hi.x, hi.y);

        if (px < POOL - 1) {
            c = c_n; wAa = wAa_n; wAb = wAb_n; wBa = wBa_n; wBb = wBb_n;
        }
    }
}

// One block per (pooled_row, roi). 128 threads x half4 = 512 channels.
__global__ __launch_bounds__(128) void roi_pool_kernel(
    float* __restrict__ out)          // [512,7,7,512]
{
    const int py  = blockIdx.x;       // 0..6
    const int roi = blockIdx.y;       // 0..511
    const int t   = threadIdx.x;      // channel group: c = 4*t

    const int rb   = roi * POOL + py;
    const int cb   = rb * POOL;
    const int4 rows = __ldg(&g_rows[rb]);
    const int mode  = __ldg(&g_mode[rb]);

    const uint2* fmt = (const uint2*)g_fmh + t;
    float4* outp = (float4*)out + (size_t)cb * 128 + t;

    const int4*  colsp = g_cols + cb;
    const uint4* waa   = g_waa + cb;
    const uint4* wab   = g_wab + cb;
    const uint4* wba   = g_wba + cb;
    const uint4* wbb   = g_wbb + cb;

    if (mode == 0)      run_row<0>(fmt, outp, colsp, waa, wab, wba, wbb, rows);
    else if (mode == 1) run_row<1>(fmt, outp, colsp, waa, wab, wba, wbb, rows);
    else                run_row<2>(fmt, outp, colsp, waa, wab, wba, wbb, rows);
}

extern "C" void kernel_launch(void* const* d_in, const int* in_sizes, int n_in,
                              void* d_out, int out_size)
{
    const float* fm   = (const float*)d_in[0];   // feature_maps [1,38,50,512]
    const float* rois = (const float*)d_in[1];   // [512,5]
    float* out = (float*)d_out;                  // [1,512,7,7,512]

    const int param_blocks = (N_CELLS + 255) / 256;          // 98
    prep_kernel<<<N8BLOCKS + param_blocks, 256>>>(fm, rois);

    dim3 grid(POOL, N_ROI);
    roi_pool_kernel<<<grid, 128>>>(out);
}

// round 15
// speedup vs baseline: 1.1497x; 1.1497x over previous
#include <cuda_runtime.h>
#include <cuda_fp16.h>

#define FM_H 38
#define FM_W 50
#define N_ROI 512
#define POOL 7
#define FM_ELEMS (FM_H * FM_W * 512)
#define N_CELLS (N_ROI * POOL * POOL)      // 25088
#define N_ROWBLK (N_ROI * POOL)            // 3584
#define N4 (FM_ELEMS / 4)                  // 243200 float4s
#define CV_PER_T 4
#define CVBLOCKS ((N4 + 256 * CV_PER_T - 1) / (256 * CV_PER_T))   // 238

// Static scratch (allocation-free).
__device__ __align__(16) static __half g_fmh[FM_ELEMS];   // fp16 feature map
__device__ static int4  g_cols[N_CELLS];       // premult col offsets (x*128)
__device__ static uint4 g_waa[N_CELLS];        // weight quads per point
__device__ static uint4 g_wab[N_CELLS];
__device__ static uint4 g_wba[N_CELLS];
__device__ static uint4 g_wbb[N_CELLS];
__device__ static int4  g_rows[N_ROWBLK];      // premult row offsets (y*50*128)
__device__ static int   g_mode[N_ROWBLK];      // row-dedup mode 0/1/2

__device__ __forceinline__ unsigned pack_h2(float f) {
    __half2 h = __float2half2_rn(f);
    return *reinterpret_cast<unsigned*>(&h);
}

// ---- merged fp32->fp16 convert (MLP=4) + per-cell parameter precompute ----
__global__ __launch_bounds__(256) void prep_kernel(
    const float* __restrict__ fm, const float* __restrict__ rois)
{
    const int b = blockIdx.x;
    if (b < CVBLOCKS) {
        // 4 independent coalesced float4 -> uint2 conversions per thread
        const int base = b * 256 * CV_PER_T + threadIdx.x;
        float4 v[CV_PER_T];
#pragma unroll
        for (int k = 0; k < CV_PER_T; ++k) {
            const int i = base + k * 256;
            if (i < N4) v[k] = ((const float4*)fm)[i];
        }
#pragma unroll
        for (int k = 0; k < CV_PER_T; ++k) {
            const int i = base + k * 256;
            if (i < N4) {
                __half2 h0 = __floats2half2_rn(v[k].x, v[k].y);
                __half2 h1 = __floats2half2_rn(v[k].z, v[k].w);
                uint2 u;
                u.x = *reinterpret_cast<unsigned*>(&h0);
                u.y = *reinterpret_cast<unsigned*>(&h1);
                ((uint2*)g_fmh)[i] = u;
            }
        }
        return;
    }
    const int idx = (b - CVBLOCKS) * 256 + threadIdx.x;   // cell id
    if (idx >= N_CELLS) return;
    const int roi = idx / (POOL * POOL);
    const int rem = idx - roi * POOL * POOL;
    const int py  = rem / POOL;
    const int px  = rem - py * POOL;

    const float* r = rois + roi * 5;
    const float x1n = r[1] * (1.0f / 800.0f);
    const float y1n = r[2] * (1.0f / 600.0f);
    const float x2n = r[3] * (1.0f / 800.0f);
    const float y2n = r[4] * (1.0f / 600.0f);
    const float dy = y2n - y1n;
    const float dx = x2n - x1n;

    int ya0, ya1, yb0, yb1;
    float wya, wyb;
    {
        const float tya = (float)(2 * py) * (1.0f / 13.0f);
        const float ysa = (y1n + tya * dy) * (float)(FM_H - 1);
        const float yfa = floorf(ysa);
        int y0 = (int)yfa; y0 = min(max(y0, 0), FM_H - 1);
        ya0 = y0; ya1 = min(y0 + 1, FM_H - 1); wya = ysa - yfa;

        const float tyb = (float)(2 * py + 1) * (1.0f / 13.0f);
        const float ysb = (y1n + tyb * dy) * (float)(FM_H - 1);
        const float yfb = floorf(ysb);
        int y1 = (int)yfb; y1 = min(max(y1, 0), FM_H - 1);
        yb0 = y1; yb1 = min(y1 + 1, FM_H - 1); wyb = ysb - yfb;
    }
    const float uya = 1.0f - wya;
    const float uyb = 1.0f - wyb;

    int mode, r2 = 0, r3 = 0;
    float waP = uya, waQ = wya, wbP, wbQ;
    if (yb0 == ya0) {
        mode = 0; wbP = uyb; wbQ = wyb;
    } else if (yb0 == ya1) {
        if (yb1 == yb0) { mode = 0; wbP = 0.0f; wbQ = uyb + wyb; }
        else { mode = 1; r2 = yb1; wbP = uyb; wbQ = wyb; }
    } else {
        mode = 2; r2 = yb0; r3 = yb1; wbP = uyb; wbQ = wyb;
    }
    if (px == 0) {
        const int rb = roi * POOL + py;
        g_rows[rb] = make_int4(ya0 * (FM_W * 128), ya1 * (FM_W * 128),
                               r2 * (FM_W * 128), r3 * (FM_W * 128));
        g_mode[rb] = mode;
    }

    int x0a, x1a, x0b, x1b;
    float wxa, wxb;
    {
        const float txa = (float)(2 * px) * (1.0f / 13.0f);
        const float xsa = (x1n + txa * dx) * (float)(FM_W - 1);
        const float xfa = floorf(xsa);
        int x0 = (int)xfa; x0 = min(max(x0, 0), FM_W - 1);
        x0a = x0; x1a = min(x0 + 1, FM_W - 1); wxa = xsa - xfa;

        const float txb = (float)(2 * px + 1) * (1.0f / 13.0f);
        const float xsb = (x1n + txb * dx) * (float)(FM_W - 1);
        const float xfb = floorf(xsb);
        int x1 = (int)xfb; x1 = min(max(x1, 0), FM_W - 1);
        x0b = x1; x1b = min(x1 + 1, FM_W - 1); wxb = xsb - xfb;
    }
    const float uxa = 1.0f - wxa;
    const float uxb = 1.0f - wxb;

    g_cols[idx] = make_int4(x0a * 128, x1a * 128, x0b * 128, x1b * 128);

    g_waa[idx] = make_uint4(pack_h2(waP * uxa), pack_h2(waP * wxa),
                            pack_h2(waQ * uxa), pack_h2(waQ * wxa));
    g_wab[idx] = make_uint4(pack_h2(waP * uxb), pack_h2(waP * wxb),
                            pack_h2(waQ * uxb), pack_h2(waQ * wxb));
    g_wba[idx] = make_uint4(pack_h2(wbP * uxa), pack_h2(wbP * wxa),
                            pack_h2(wbQ * uxa), pack_h2(wbQ * wxa));
    g_wbb[idx] = make_uint4(pack_h2(wbP * uxb), pack_h2(wbP * wxb),
                            pack_h2(wbQ * uxb), pack_h2(wbQ * wxb));
}

// ---- half4 helpers ----
struct h4 { __half2 a, b; };

__device__ __forceinline__ h4 ld_h4(const uint2* __restrict__ p) {
    const uint2 u = __ldg(p);              // read-only path, hoistable
    h4 v;
    v.a = *reinterpret_cast<const __half2*>(&u.x);
    v.b = *reinterpret_cast<const __half2*>(&u.y);
    return v;
}

__device__ __forceinline__ __half2 as_h2(unsigned u) {
    return *reinterpret_cast<__half2*>(&u);
}

__device__ __forceinline__ h4 quad4h(h4 A, h4 B, h4 C, h4 D,
                                     __half2 w0, __half2 w1, __half2 w2, __half2 w3) {
    h4 r;
    r.a = __hfma2(D.a, w3, __hfma2(C.a, w2, __hfma2(B.a, w1, __hmul2(A.a, w0))));
    r.b = __hfma2(D.b, w3, __hfma2(C.b, w2, __hfma2(B.b, w1, __hmul2(A.b, w0))));
    return r;
}

__device__ __forceinline__ h4 max4h(h4 x, h4 y) {
    h4 r;
    r.a = __hmax2(x.a, y.a);
    r.b = __hmax2(x.b, y.b);
    return r;
}

// MODE 0: rows (r0,r1) for both point pairs. MODE 1: pair-b on (r1,r2).
// MODE 2: pair-b on (r2,r3). Straight-line across 7 cells; params come from
// SMEM (broadcast LDS, no global chains inside the loop).
template <int MODE>
__device__ __forceinline__ void run_row(
    const uint2* __restrict__ fmt, float4* __restrict__ outp,
    const int4* s_cols,
    const uint4* s_waa, const uint4* s_wab,
    const uint4* s_wba, const uint4* s_wbb,
    int4 rows)
{
#pragma unroll
    for (int px = 0; px < POOL; ++px) {
        const int4  c   = s_cols[px];
        const uint4 wAa = s_waa[px];
        const uint4 wAb = s_wab[px];
        const uint4 wBa = s_wba[px];
        const uint4 wBb = s_wbb[px];

        const h4 vA0a = ld_h4(fmt + (rows.x + c.x));
        const h4 vA1a = ld_h4(fmt + (rows.x + c.y));
        const h4 vA0b = ld_h4(fmt + (rows.x + c.z));
        const h4 vA1b = ld_h4(fmt + (rows.x + c.w));
        const h4 vB0a = ld_h4(fmt + (rows.y + c.x));
        const h4 vB1a = ld_h4(fmt + (rows.y + c.y));
        const h4 vB0b = ld_h4(fmt + (rows.y + c.z));
        const h4 vB1b = ld_h4(fmt + (rows.y + c.w));

        h4 vC0a, vC1a, vC0b, vC1b, vD0a, vD1a, vD0b, vD1b;
        if (MODE == 0) {
            vC0a = vA0a; vC1a = vA1a; vC0b = vA0b; vC1b = vA1b;
            vD0a = vB0a; vD1a = vB1a; vD0b = vB0b; vD1b = vB1b;
        } else if (MODE == 1) {
            vC0a = vB0a; vC1a = vB1a; vC0b = vB0b; vC1b = vB1b;
            vD0a = ld_h4(fmt + (rows.z + c.x));
            vD1a = ld_h4(fmt + (rows.z + c.y));
            vD0b = ld_h4(fmt + (rows.z + c.z));
            vD1b = ld_h4(fmt + (rows.z + c.w));
        } else {
            vC0a = ld_h4(fmt + (rows.z + c.x));
            vC1a = ld_h4(fmt + (rows.z + c.y));
            vC0b = ld_h4(fmt + (rows.z + c.z));
            vC1b = ld_h4(fmt + (rows.z + c.w));
            vD0a = ld_h4(fmt + (rows.w + c.x));
            vD1a = ld_h4(fmt + (rows.w + c.y));
            vD0b = ld_h4(fmt + (rows.w + c.z));
            vD1b = ld_h4(fmt + (rows.w + c.w));
        }

        const h4 s_aa = quad4h(vA0a, vA1a, vB0a, vB1a,
                               as_h2(wAa.x), as_h2(wAa.y), as_h2(wAa.z), as_h2(wAa.w));
        const h4 s_ab = quad4h(vA0b, vA1b, vB0b, vB1b,
                               as_h2(wAb.x), as_h2(wAb.y), as_h2(wAb.z), as_h2(wAb.w));
        const h4 s_ba = quad4h(vC0a, vC1a, vD0a, vD1a,
                               as_h2(wBa.x), as_h2(wBa.y), as_h2(wBa.z), as_h2(wBa.w));
        const h4 s_bb = quad4h(vC0b, vC1b, vD0b, vD1b,
                               as_h2(wBb.x), as_h2(wBb.y), as_h2(wBb.z), as_h2(wBb.w));

        const h4 m = max4h(max4h(s_aa, s_ab), max4h(s_ba, s_bb));
        const float2 lo = __half22float2(m.a);
        const float2 hi = __half22float2(m.b);
        outp[px * 128] = make_float4(lo.x, lo.y, hi.x, hi.y);
    }
}

// One block per (pooled_row, roi). 128 threads x half4 = 512 channels.
// Threads 0-36 stage this block's params into SMEM, then all read via
// broadcast LDS inside the branch-free cell loop.
__global__ __launch_bounds__(128) void roi_pool_kernel(
    float* __restrict__ out)          // [512,7,7,512]
{
    const int py  = blockIdx.x;       // 0..6
    const int roi = blockIdx.y;       // 0..511
    const int t   = threadIdx.x;      // channel group: c = 4*t

    const int rb = roi * POOL + py;
    const int cb = rb * POOL;

    __shared__ int4  s_cols[POOL];
    __shared__ uint4 s_waa[POOL], s_wab[POOL], s_wba[POOL], s_wbb[POOL];
    __shared__ int4  s_rows;
    __shared__ int   s_mode;

    if (t < POOL)            s_cols[t]      = __ldg(&g_cols[cb + t]);
    else if (t < 2 * POOL)   s_waa[t - POOL]     = __ldg(&g_waa[cb + t - POOL]);
    else if (t < 3 * POOL)   s_wab[t - 2 * POOL] = __ldg(&g_wab[cb + t - 2 * POOL]);
    else if (t < 4 * POOL)   s_wba[t - 3 * POOL] = __ldg(&g_wba[cb + t - 3 * POOL]);
    else if (t < 5 * POOL)   s_wbb[t - 4 * POOL] = __ldg(&g_wbb[cb + t - 4 * POOL]);
    else if (t == 5 * POOL)  s_rows = __ldg(&g_rows[rb]);
    else if (t == 5 * POOL + 1) s_mode = g_mode[rb];
    __syncthreads();

    const int4 rows = s_rows;
    const int  mode = s_mode;

    const uint2* fmt = (const uint2*)g_fmh + t;
    float4* outp = (float4*)out + (size_t)cb * 128 + t;

    if (mode == 0)      run_row<0>(fmt, outp, s_cols, s_waa, s_wab, s_wba, s_wbb, rows);
    else if (mode == 1) run_row<1>(fmt, outp, s_cols, s_waa, s_wab, s_wba, s_wbb, rows);
    else                run_row<2>(fmt, outp, s_cols, s_waa, s_wab, s_wba, s_wbb, rows);
}

extern "C" void kernel_launch(void* const* d_in, const int* in_sizes, int n_in,
                              void* d_out, int out_size)
{
    const float* fm   = (const float*)d_in[0];   // feature_maps [1,38,50,512]
    const float* rois = (const float*)d_in[1];   // [512,5]
    float* out = (float*)d_out;                  // [1,512,7,7,512]

    const int param_blocks = (N_CELLS + 255) / 256;          // 98
    prep_kernel<<<CVBLOCKS + param_blocks, 256>>>(fm, rois);

    dim3 grid(POOL, N_ROI);
    roi_pool_kernel<<<grid, 128>>>(out);
}